// round 15
// baseline (speedup 1.0000x reference)
#include <cuda_runtime.h>
#include <cuda_fp16.h>
#include <math.h>
#include <stdint.h>

// Problem constants
#define BB 32
#define TT 256
#define EE 256
#define HH 512
#define G4 2048          // 4*H
#define VV 32000
#define BT 8192          // B*T

// ---------------------------------------------------------------------------
// Scratch (no allocations allowed -> __device__ globals)
// ---------------------------------------------------------------------------
__device__ int g_idx[BT];
__device__ float g_xg[(size_t)BT * G4];      // [t][b][4H] gate preactivations
__device__ __half g_hs_h[(size_t)BT * HH];   // fp16 [t][b][k] hidden states
__device__ __half g_emb_h[(size_t)VV * EE];  // fp16 embed_w
__device__ __half g_wih_h[(size_t)G4 * EE];  // fp16 w_ih
__device__ __half g_fcw_h[(size_t)VV * HH];  // fp16 fc_w
__device__ __half g_lnw_h[(size_t)HH * HH];  // fp16 ln_w
__device__ unsigned g_flags[128];            // per-block step completion flags

// ---------------------------------------------------------------------------
// Small helpers
// ---------------------------------------------------------------------------
__device__ __forceinline__ uint32_t f16x2(float lo, float hi) {
    uint32_t r;
    asm("cvt.rn.f16x2.f32 %0, %1, %2;" : "=r"(r) : "f"(hi), "f"(lo));
    return r;
}
__device__ __forceinline__ uint32_t smem_u32(const void* p) {
    uint32_t a;
    asm("{ .reg .u64 t; cvta.to.shared.u64 t, %1; cvt.u32.u64 %0, t; }"
        : "=r"(a) : "l"(p));
    return a;
}
__device__ __forceinline__ void cp16(uint32_t dst, const void* src) {
    asm volatile("cp.async.cg.shared.global [%0], [%1], 16;"
                 :: "r"(dst), "l"(src) : "memory");
}
#define CP_COMMIT() asm volatile("cp.async.commit_group;" ::: "memory")
#define CP_WAIT1()  asm volatile("cp.async.wait_group 1;" ::: "memory")
#define CP_WAIT0()  asm volatile("cp.async.wait_group 0;" ::: "memory")

__device__ __forceinline__ void mma_f16(float* c, const uint32_t* a,
                                        const uint32_t* b) {
    asm volatile(
        "mma.sync.aligned.m16n8k16.row.col.f32.f16.f16.f32 "
        "{%0,%1,%2,%3}, {%4,%5,%6,%7}, {%8,%9}, {%0,%1,%2,%3};"
        : "+f"(c[0]), "+f"(c[1]), "+f"(c[2]), "+f"(c[3])
        : "r"(a[0]), "r"(a[1]), "r"(a[2]), "r"(a[3]), "r"(b[0]), "r"(b[1]));
}

// ---------------------------------------------------------------------------
// Token index decode + flag reset (runs before the LSTM every launch)
// ---------------------------------------------------------------------------
__global__ void decode_idx_kernel(const void* __restrict__ xin) {
    int i = blockIdx.x * blockDim.x + threadIdx.x;
    if (i < 128) g_flags[i] = 0;
    if (i >= BT) return;
    const long long* x64 = (const long long*)xin;
    bool is64 = true;
#pragma unroll
    for (int j = 0; j < 8; j++) {
        long long v = x64[j];
        if (v < 0 || v >= VV) is64 = false;
    }
    g_idx[i] = is64 ? (int)x64[i] : ((const int*)xin)[i];
}

// ---------------------------------------------------------------------------
// Convert fp32 -> fp16 (RN), 8 elements per thread.
// ---------------------------------------------------------------------------
__global__ void cvt_f16_kernel(__half* __restrict__ dst,
                               const float* __restrict__ src, int n8) {
    int i = blockIdx.x * blockDim.x + threadIdx.x;
    if (i >= n8) return;
    float4 v0 = ((const float4*)src)[2 * i];
    float4 v1 = ((const float4*)src)[2 * i + 1];
    uint4 o = make_uint4(f16x2(v0.x, v0.y), f16x2(v0.z, v0.w),
                         f16x2(v1.x, v1.y), f16x2(v1.z, v1.w));
    ((uint4*)dst)[i] = o;
}

// ---------------------------------------------------------------------------
// fp16 mma GEMM (m16n8k16) — unified for xg / fc / ln (proven R12 kernel):
// CTA 128x128, BK=32, 256 threads, 8 warps (2M x 4N), warp tile 64x32.
// Row-major smem tiles, stride 20 words; cp.async.cg staging, 2 stages.
//   MODE 0: fc (A=g_hs_h remap, K=512, out stride VV)
//   MODE 1: ln (A=g_hs_h remap, K=512, out stride HH)
//   MODE 2: xg (A=g_emb_h gathered via g_idx, K=256, out -> g_xg remap)
// ---------------------------------------------------------------------------
#define BS 20
#define BTILE_W (128 * BS)
#define BBUF_W (2 * BTILE_W)
#define BMM_SMEM_BYTES (2 * BBUF_W * 4)   // 40960

template <int KITERS, int MODE>
__global__ __launch_bounds__(256, 2) void gemm_f16(
    const __half* __restrict__ Wh,   // [N][K] fp16
    const float* __restrict__ bias,  // [N]
    float* __restrict__ outp)
{
    constexpr int K = KITERS * 32;
    extern __shared__ uint32_t smem[];
    const uint32_t sbase = smem_u32(smem);
    const int tid = threadIdx.x;
    const int w = tid >> 5;
    const int lane = tid & 31;
    const int g = lane >> 2;
    const int t = lane & 3;
    const int wm = w >> 2;
    const int wn = w & 3;
    const int by = blockIdx.y;
    const int m0 = by * 128;
    const int n0 = blockIdx.x * 128;

    const int srow = tid >> 2;
    const int schk = (tid & 3) * 8;
    const __half* aP[2];
    const __half* bP[2];
#pragma unroll
    for (int q = 0; q < 2; q++) {
        const int r = srow + q * 64;
        if (MODE == 2) {
            aP[q] = g_emb_h + (size_t)g_idx[m0 + r] * EE + schk;
        } else {
            aP[q] = g_hs_h +
                    ((size_t)((by & 1) * 128 + r) * 32 + (size_t)(by >> 1)) * HH +
                    schk;
        }
        bP[q] = Wh + (size_t)(n0 + r) * K + schk;
    }
    const uint32_t stg = sbase + (uint32_t)srow * 80 + (uint32_t)(tid & 3) * 16;

    float c[4][4][4];
#pragma unroll
    for (int mi = 0; mi < 4; mi++)
#pragma unroll
        for (int ni = 0; ni < 4; ni++)
#pragma unroll
            for (int q = 0; q < 4; q++) c[mi][ni][q] = 0.f;

    auto ISSUE = [&](int s) {
        const uint32_t aD = stg + (s & 1) * (BBUF_W * 4);
        const uint32_t bD = aD + BTILE_W * 4;
        const int k0 = s * 32;
#pragma unroll
        for (int q = 0; q < 2; q++) {
            cp16(aD + q * (64 * 80), aP[q] + k0);
            cp16(bD + q * (64 * 80), bP[q] + k0);
        }
        CP_COMMIT();
    };

    ISSUE(0);
    for (int s = 0; s < KITERS; s++) {
        if (s + 1 < KITERS) { ISSUE(s + 1); CP_WAIT1(); }
        else                { CP_WAIT0(); }
        __syncthreads();

        const uint32_t* aC = smem + (s & 1) * BBUF_W + (wm * 64 + g) * BS + t;
        const uint32_t* bC = smem + (s & 1) * BBUF_W + BTILE_W +
                             (wn * 32 + g) * BS + t;
#pragma unroll
        for (int kk = 0; kk < 2; kk++) {
            uint32_t af[4][4];
#pragma unroll
            for (int mi = 0; mi < 4; mi++) {
                const uint32_t* p = aC + mi * (16 * BS) + kk * 8;
                af[mi][0] = p[0];
                af[mi][1] = p[8 * BS];
                af[mi][2] = p[4];
                af[mi][3] = p[8 * BS + 4];
            }
            uint32_t bf[4][2];
#pragma unroll
            for (int ni = 0; ni < 4; ni++) {
                const uint32_t* p = bC + ni * (8 * BS) + kk * 8;
                bf[ni][0] = p[0];
                bf[ni][1] = p[4];
            }
#pragma unroll
            for (int mi = 0; mi < 4; mi++)
#pragma unroll
                for (int ni = 0; ni < 4; ni++)
                    mma_f16(c[mi][ni], af[mi], bf[ni]);
        }
        __syncthreads();
    }

    const int col0 = n0 + wn * 32 + 2 * t;
    float2 bias2[4];
#pragma unroll
    for (int ni = 0; ni < 4; ni++)
        bias2[ni] = *(const float2*)(bias + col0 + ni * 8);
#pragma unroll
    for (int mi = 0; mi < 4; mi++) {
        int gm = m0 + wm * 64 + mi * 16 + g;
        float *r0, *r1;
        if (MODE == 0) {
            r0 = outp + (size_t)gm * VV;
            r1 = outp + (size_t)(gm + 8) * VV;
        } else if (MODE == 1) {
            r0 = outp + (size_t)gm * HH;
            r1 = outp + (size_t)(gm + 8) * HH;
        } else {
            int gm8 = gm + 8;
            r0 = g_xg + (size_t)((gm & 255) * 32 + (gm >> 8)) * G4;
            r1 = g_xg + (size_t)((gm8 & 255) * 32 + (gm8 >> 8)) * G4;
        }
#pragma unroll
        for (int ni = 0; ni < 4; ni++) {
            float2 v0 = make_float2(c[mi][ni][0] + bias2[ni].x,
                                    c[mi][ni][1] + bias2[ni].y);
            float2 v1 = make_float2(c[mi][ni][2] + bias2[ni].x,
                                    c[mi][ni][3] + bias2[ni].y);
            *(float2*)(r0 + col0 + ni * 8) = v0;
            *(float2*)(r1 + col0 + ni * 8) = v1;
        }
    }
}

// ---------------------------------------------------------------------------
// Persistent LSTM kernel — HMMA recurrence + flag-based step ordering:
//   G[16][32b] = W_hh[16][512] (fp16 reg fragments) x H[512][32] (fp16 smem),
//   K split 8 ways across warps, 8-way smem reduce (proven R14 structure).
//   Step ordering via 128 per-block monotonic flags with release/acquire:
//   no same-address atomic serialization, no gpu-scope fences (L1 flushes).
// 128 blocks x 256 threads, 1/SM, all co-resident.
// ---------------------------------------------------------------------------
#define LSTM_BLOCKS 128
#define HSTRW 260                     // hH row stride in 32-bit words
#define LSTM_HH_W (32 * HSTRW)        // 8320 words
#define LSTM_RED_W (512 * 9)          // 4608 words
#define LSTM_SMEM_WORDS (LSTM_HH_W + LSTM_RED_W + 512 + 128 + 16)
#define LSTM_SMEM_BYTES (LSTM_SMEM_WORDS * 4)   // 54336

__device__ __forceinline__ int lstm_grow(int j0, int r) {
    return (r >> 2) * 512 + j0 + (r & 3);   // gate g = r>>2, unit u = r&3
}

__global__ __launch_bounds__(256) void lstm_kernel(const float* __restrict__ w_hh,
                                                   const float* __restrict__ b_hh) {
    extern __shared__ uint32_t sw[];
    uint32_t* hH  = sw;                          // [32 b][260 w] fp16x2
    float* sRed   = (float*)(sw + LSTM_HH_W);    // [512 o][9 pad] (8 warps)
    float* sGate  = sRed + LSTM_RED_W;           // [16 r][32 b]
    float* sC     = sGate + 512;                 // [4 u][32 b]
    float* sBh    = sC + 128;                    // [16]
    const uint32_t hHb = smem_u32(hH);

    const int tid = threadIdx.x;
    const int w = tid >> 5;
    const int lane = tid & 31;
    const int g = lane >> 2;
    const int t = tid & 3;   // == lane & 3 for fragment math
    const int j0 = blockIdx.x * 4;
    const int kw = w * 64;                       // warp's K-slice base (elems)

    // Register-resident W_hh fragments (fp16): rows g / g+8, warp k-slice.
    uint32_t wa[4][4];
    {
        const float* r0p = w_hh + (size_t)lstm_grow(j0, g) * 512;
        const float* r1p = w_hh + (size_t)lstm_grow(j0, g + 8) * 512;
#pragma unroll
        for (int kk = 0; kk < 4; kk++) {
            int kb = kw + kk * 16 + 2 * (lane & 3);
            wa[kk][0] = f16x2(r0p[kb],     r0p[kb + 1]);
            wa[kk][1] = f16x2(r1p[kb],     r1p[kb + 1]);
            wa[kk][2] = f16x2(r0p[kb + 8], r0p[kb + 9]);
            wa[kk][3] = f16x2(r1p[kb + 8], r1p[kb + 9]);
        }
    }
    if (tid < 16) sBh[tid] = b_hh[lstm_grow(j0, tid)];
    if (tid < 128) sC[tid] = 0.f;
    for (int i = tid; i < LSTM_HH_W; i += 256) hH[i] = 0u;   // h(-1) = 0
    __syncthreads();

    // Per-thread reduce coordinates (outputs o=2*tid, 2*tid+1; same row rr)
    const int oo = tid * 2;
    const int rr = oo >> 5;
    const int ob = oo & 31;
    const float bh_r = sBh[rr];   // safe: sBh written before __syncthreads

    for (int ts = 0; ts < TT; ts++) {
        // Prefetch this step's xg contribution (independent of h ordering)
        const float* xp = g_xg + (size_t)(ts * 32 + ob) * G4 + lstm_grow(j0, rr);
        float x0 = xp[0];
        float x1 = xp[G4];

        if (ts > 0) {
            // Wait for all 128 producer flags of step ts (parallel acquire polls)
            if (tid < 128) {
                unsigned v;
                do {
                    asm volatile("ld.acquire.gpu.global.b32 %0, [%1];"
                                 : "=r"(v) : "l"(g_flags + tid) : "memory");
                } while (v < (unsigned)ts);
            }
            __syncthreads();
            // Broadcast h(t-1): 32KB fp16, linear cp.async (L2-direct)
            const __half* src = g_hs_h + (size_t)(ts - 1) * 32 * 512;
#pragma unroll
            for (int ii = 0; ii < 8; ii++) {
                int idx = tid + 256 * ii;
                int b = idx >> 6, cc = idx & 63;
                cp16(hHb + (uint32_t)(b * HSTRW + cc * 4) * 4, src + idx * 8);
            }
            CP_COMMIT();
            CP_WAIT0();
            __syncthreads();
        }

        // HMMA: 4 n-tiles x 4 k-steps over this warp's K-slice
        float acc[4][4];
#pragma unroll
        for (int ni = 0; ni < 4; ni++)
#pragma unroll
            for (int q = 0; q < 4; q++) acc[ni][q] = 0.f;

        const uint32_t* hBase = hH + g * HSTRW + (kw >> 1) + (lane & 3);
#pragma unroll
        for (int kk = 0; kk < 4; kk++) {
#pragma unroll
            for (int ni = 0; ni < 4; ni++) {
                const uint32_t* p = hBase + ni * (8 * HSTRW) + kk * 8;
                uint32_t bf[2] = {p[0], p[4]};
                mma_f16(acc[ni], wa[kk], bf);
            }
        }
        // Partial store: C rows g / g+8, cols 2t,2t+1 per n-tile
#pragma unroll
        for (int ni = 0; ni < 4; ni++) {
            int o0 = g * 32 + ni * 8 + 2 * (lane & 3);
            int o1 = (g + 8) * 32 + ni * 8 + 2 * (lane & 3);
            sRed[o0 * 9 + w]       = acc[ni][0];
            sRed[(o0 + 1) * 9 + w] = acc[ni][1];
            sRed[o1 * 9 + w]       = acc[ni][2];
            sRed[(o1 + 1) * 9 + w] = acc[ni][3];
        }
        __syncthreads();

        // Reduce 8 warp partials, add prefetched xg + b_hh
        {
            const float* pr = sRed + oo * 9;
            float s0 = 0.f, s1 = 0.f;
#pragma unroll
            for (int j = 0; j < 8; j++) { s0 += pr[j]; s1 += pr[9 + j]; }
            sGate[oo]     = s0 + x0 + bh_r;
            sGate[oo + 1] = s1 + x1 + bh_r;
        }
        __syncthreads();

        // Activations + state update (gate order i,f,g,o)
        if (tid < 128) {
            int u = tid & 3, b = tid >> 2;
            float gi = sGate[(0 + u) * 32 + b];
            float gf = sGate[(4 + u) * 32 + b];
            float gg = sGate[(8 + u) * 32 + b];
            float go = sGate[(12 + u) * 32 + b];
            float cc = sC[u * 32 + b];
            float si = 1.f / (1.f + expf(-gi));
            float sf = 1.f / (1.f + expf(-gf));
            float so = 1.f / (1.f + expf(-go));
            cc = sf * cc + si * tanhf(gg);
            float h = so * tanhf(cc);
            sC[u * 32 + b] = cc;
            g_hs_h[(size_t)(ts * 32 + b) * 512 + j0 + u] = __float2half(h);
        }
        __syncthreads();
        // Publish: this block's h slice for step ts is globally visible
        if (tid == 0) {
            asm volatile("st.release.gpu.global.b32 [%0], %1;"
                         :: "l"(g_flags + blockIdx.x), "r"((unsigned)(ts + 1))
                         : "memory");
        }
    }
}

// ---------------------------------------------------------------------------
// Launch
// ---------------------------------------------------------------------------
extern "C" void kernel_launch(void* const* d_in, const int* in_sizes, int n_in,
                              void* d_out, int out_size) {
    const void*  x       = d_in[0];
    const float* embed_w = (const float*)d_in[1];
    const float* w_ih    = (const float*)d_in[2];
    const float* w_hh    = (const float*)d_in[3];
    const float* b_ih    = (const float*)d_in[4];
    const float* b_hh    = (const float*)d_in[5];
    const float* fc_w    = (const float*)d_in[6];
    const float* fc_b    = (const float*)d_in[7];
    const float* ln_w    = (const float*)d_in[8];
    const float* ln_b    = (const float*)d_in[9];

    float* out    = (float*)d_out;
    float* states = out + (size_t)BT * VV;

    __half *emb_h, *wih_h, *fcw_h, *lnw_h;
    cudaGetSymbolAddress((void**)&emb_h, g_emb_h);
    cudaGetSymbolAddress((void**)&wih_h, g_wih_h);
    cudaGetSymbolAddress((void**)&fcw_h, g_fcw_h);
    cudaGetSymbolAddress((void**)&lnw_h, g_lnw_h);

    // 1) decode token indices + reset LSTM step flags
    decode_idx_kernel<<<BT / 256, 256>>>(x);

    // 2) pre-convert all GEMM operands to fp16 (RN)
    cvt_f16_kernel<<<(VV * EE / 8) / 256, 256>>>(emb_h, embed_w, VV * EE / 8);
    cvt_f16_kernel<<<(G4 * EE / 8) / 256, 256>>>(wih_h, w_ih, G4 * EE / 8);
    cvt_f16_kernel<<<(VV * HH / 8) / 256, 256>>>(fcw_h, fc_w, VV * HH / 8);
    cvt_f16_kernel<<<(HH * HH / 8) / 256, 256>>>(lnw_h, ln_w, HH * HH / 8);

    // 3) xg = embed[x] @ w_ih^T + b_ih   (tensor fp16, K=256)
    cudaFuncSetAttribute(gemm_f16<8, 2>,
                         cudaFuncAttributeMaxDynamicSharedMemorySize, BMM_SMEM_BYTES);
    gemm_f16<8, 2><<<dim3(G4 / 128, BT / 128), 256, BMM_SMEM_BYTES>>>(
        wih_h, b_ih, nullptr);

    // 4) sequential LSTM (fp32 c / gates; fp16 h; HMMA recurrence)
    cudaFuncSetAttribute(lstm_kernel, cudaFuncAttributeMaxDynamicSharedMemorySize,
                         LSTM_SMEM_BYTES);
    lstm_kernel<<<LSTM_BLOCKS, 256, LSTM_SMEM_BYTES>>>(w_hh, b_hh);

    // 5) out = hs @ fc_w^T + fc_b   (tensor fp16, K=512)
    cudaFuncSetAttribute(gemm_f16<16, 0>,
                         cudaFuncAttributeMaxDynamicSharedMemorySize, BMM_SMEM_BYTES);
    gemm_f16<16, 0><<<dim3(VV / 128, BT / 128), 256, BMM_SMEM_BYTES>>>(
        fcw_h, fc_b, out);

    // 6) states = hs @ ln_w^T + ln_b   (tensor fp16, K=512)
    cudaFuncSetAttribute(gemm_f16<16, 1>,
                         cudaFuncAttributeMaxDynamicSharedMemorySize, BMM_SMEM_BYTES);
    gemm_f16<16, 1><<<dim3(HH / 128, BT / 128), 256, BMM_SMEM_BYTES>>>(
        lnw_h, ln_b, states);
}

// round 16
// speedup vs baseline: 1.2721x; 1.2721x over previous
#include <cuda_runtime.h>
#include <cuda_fp16.h>
#include <math.h>
#include <stdint.h>

// Problem constants
#define BB 32
#define TT 256
#define EE 256
#define HH 512
#define G4 2048          // 4*H
#define VV 32000
#define BT 8192          // B*T

// ---------------------------------------------------------------------------
// Scratch (no allocations allowed -> __device__ globals)
// ---------------------------------------------------------------------------
__device__ int g_idx[BT];
__device__ float g_xg[(size_t)BT * G4];      // [t][b][4H] gate preactivations
__device__ __half g_hs_h[(size_t)BT * HH];   // fp16 [t][b][k] hidden states
__device__ __half g_emb_h[(size_t)VV * EE];  // fp16 embed_w
__device__ __half g_wih_h[(size_t)G4 * EE];  // fp16 w_ih
__device__ __half g_fcw_h[(size_t)VV * HH];  // fp16 fc_w
__device__ __half g_lnw_h[(size_t)HH * HH];  // fp16 ln_w
__device__ unsigned g_bar_count = 0;
__device__ volatile unsigned g_bar_gen = 0;

// ---------------------------------------------------------------------------
// Small helpers
// ---------------------------------------------------------------------------
__device__ __forceinline__ uint32_t f16x2(float lo, float hi) {
    uint32_t r;
    asm("cvt.rn.f16x2.f32 %0, %1, %2;" : "=r"(r) : "f"(hi), "f"(lo));
    return r;
}
__device__ __forceinline__ uint32_t smem_u32(const void* p) {
    uint32_t a;
    asm("{ .reg .u64 t; cvta.to.shared.u64 t, %1; cvt.u32.u64 %0, t; }"
        : "=r"(a) : "l"(p));
    return a;
}
__device__ __forceinline__ void cp16(uint32_t dst, const void* src) {
    asm volatile("cp.async.cg.shared.global [%0], [%1], 16;"
                 :: "r"(dst), "l"(src) : "memory");
}
#define CP_COMMIT() asm volatile("cp.async.commit_group;" ::: "memory")
#define CP_WAIT1()  asm volatile("cp.async.wait_group 1;" ::: "memory")
#define CP_WAIT0()  asm volatile("cp.async.wait_group 0;" ::: "memory")

__device__ __forceinline__ void mma_f16(float* c, const uint32_t* a,
                                        const uint32_t* b) {
    asm volatile(
        "mma.sync.aligned.m16n8k16.row.col.f32.f16.f16.f32 "
        "{%0,%1,%2,%3}, {%4,%5,%6,%7}, {%8,%9}, {%0,%1,%2,%3};"
        : "+f"(c[0]), "+f"(c[1]), "+f"(c[2]), "+f"(c[3])
        : "r"(a[0]), "r"(a[1]), "r"(a[2]), "r"(a[3]), "r"(b[0]), "r"(b[1]));
}

// ---------------------------------------------------------------------------
// Token index decode: handles both int64 and int32 storage of x
// ---------------------------------------------------------------------------
__global__ void decode_idx_kernel(const void* __restrict__ xin) {
    int i = blockIdx.x * blockDim.x + threadIdx.x;
    if (i >= BT) return;
    const long long* x64 = (const long long*)xin;
    bool is64 = true;
#pragma unroll
    for (int j = 0; j < 8; j++) {
        long long v = x64[j];
        if (v < 0 || v >= VV) is64 = false;
    }
    g_idx[i] = is64 ? (int)x64[i] : ((const int*)xin)[i];
}

// ---------------------------------------------------------------------------
// Convert fp32 -> fp16 (RN), 8 elements per thread.
// ---------------------------------------------------------------------------
__global__ void cvt_f16_kernel(__half* __restrict__ dst,
                               const float* __restrict__ src, int n8) {
    int i = blockIdx.x * blockDim.x + threadIdx.x;
    if (i >= n8) return;
    float4 v0 = ((const float4*)src)[2 * i];
    float4 v1 = ((const float4*)src)[2 * i + 1];
    uint4 o = make_uint4(f16x2(v0.x, v0.y), f16x2(v0.z, v0.w),
                         f16x2(v1.x, v1.y), f16x2(v1.z, v1.w));
    ((uint4*)dst)[i] = o;
}

// ---------------------------------------------------------------------------
// fp16 mma GEMM (m16n8k16) — unified for xg / fc / ln (proven R12 kernel):
// CTA 128x128, BK=32, 256 threads, 8 warps (2M x 4N), warp tile 64x32.
// Row-major smem tiles, stride 20 words; cp.async.cg staging, 2 stages.
//   MODE 0: fc (A=g_hs_h remap, K=512, out stride VV)
//   MODE 1: ln (A=g_hs_h remap, K=512, out stride HH)
//   MODE 2: xg (A=g_emb_h gathered via g_idx, K=256, out -> g_xg remap)
// ---------------------------------------------------------------------------
#define BS 20
#define BTILE_W (128 * BS)
#define BBUF_W (2 * BTILE_W)
#define BMM_SMEM_BYTES (2 * BBUF_W * 4)   // 40960

template <int KITERS, int MODE>
__global__ __launch_bounds__(256, 2) void gemm_f16(
    const __half* __restrict__ Wh,   // [N][K] fp16
    const float* __restrict__ bias,  // [N]
    float* __restrict__ outp)
{
    constexpr int K = KITERS * 32;
    extern __shared__ uint32_t smem[];
    const uint32_t sbase = smem_u32(smem);
    const int tid = threadIdx.x;
    const int w = tid >> 5;
    const int lane = tid & 31;
    const int g = lane >> 2;
    const int t = lane & 3;
    const int wm = w >> 2;
    const int wn = w & 3;
    const int by = blockIdx.y;
    const int m0 = by * 128;
    const int n0 = blockIdx.x * 128;

    const int srow = tid >> 2;
    const int schk = (tid & 3) * 8;
    const __half* aP[2];
    const __half* bP[2];
#pragma unroll
    for (int q = 0; q < 2; q++) {
        const int r = srow + q * 64;
        if (MODE == 2) {
            aP[q] = g_emb_h + (size_t)g_idx[m0 + r] * EE + schk;
        } else {
            aP[q] = g_hs_h +
                    ((size_t)((by & 1) * 128 + r) * 32 + (size_t)(by >> 1)) * HH +
                    schk;
        }
        bP[q] = Wh + (size_t)(n0 + r) * K + schk;
    }
    const uint32_t stg = sbase + (uint32_t)srow * 80 + (uint32_t)(tid & 3) * 16;

    float c[4][4][4];
#pragma unroll
    for (int mi = 0; mi < 4; mi++)
#pragma unroll
        for (int ni = 0; ni < 4; ni++)
#pragma unroll
            for (int q = 0; q < 4; q++) c[mi][ni][q] = 0.f;

    auto ISSUE = [&](int s) {
        const uint32_t aD = stg + (s & 1) * (BBUF_W * 4);
        const uint32_t bD = aD + BTILE_W * 4;
        const int k0 = s * 32;
#pragma unroll
        for (int q = 0; q < 2; q++) {
            cp16(aD + q * (64 * 80), aP[q] + k0);
            cp16(bD + q * (64 * 80), bP[q] + k0);
        }
        CP_COMMIT();
    };

    ISSUE(0);
    for (int s = 0; s < KITERS; s++) {
        if (s + 1 < KITERS) { ISSUE(s + 1); CP_WAIT1(); }
        else                { CP_WAIT0(); }
        __syncthreads();

        const uint32_t* aC = smem + (s & 1) * BBUF_W + (wm * 64 + g) * BS + t;
        const uint32_t* bC = smem + (s & 1) * BBUF_W + BTILE_W +
                             (wn * 32 + g) * BS + t;
#pragma unroll
        for (int kk = 0; kk < 2; kk++) {
            uint32_t af[4][4];
#pragma unroll
            for (int mi = 0; mi < 4; mi++) {
                const uint32_t* p = aC + mi * (16 * BS) + kk * 8;
                af[mi][0] = p[0];
                af[mi][1] = p[8 * BS];
                af[mi][2] = p[4];
                af[mi][3] = p[8 * BS + 4];
            }
            uint32_t bf[4][2];
#pragma unroll
            for (int ni = 0; ni < 4; ni++) {
                const uint32_t* p = bC + ni * (8 * BS) + kk * 8;
                bf[ni][0] = p[0];
                bf[ni][1] = p[4];
            }
#pragma unroll
            for (int mi = 0; mi < 4; mi++)
#pragma unroll
                for (int ni = 0; ni < 4; ni++)
                    mma_f16(c[mi][ni], af[mi], bf[ni]);
        }
        __syncthreads();
    }

    const int col0 = n0 + wn * 32 + 2 * t;
    float2 bias2[4];
#pragma unroll
    for (int ni = 0; ni < 4; ni++)
        bias2[ni] = *(const float2*)(bias + col0 + ni * 8);
#pragma unroll
    for (int mi = 0; mi < 4; mi++) {
        int gm = m0 + wm * 64 + mi * 16 + g;
        float *r0, *r1;
        if (MODE == 0) {
            r0 = outp + (size_t)gm * VV;
            r1 = outp + (size_t)(gm + 8) * VV;
        } else if (MODE == 1) {
            r0 = outp + (size_t)gm * HH;
            r1 = outp + (size_t)(gm + 8) * HH;
        } else {
            int gm8 = gm + 8;
            r0 = g_xg + (size_t)((gm & 255) * 32 + (gm >> 8)) * G4;
            r1 = g_xg + (size_t)((gm8 & 255) * 32 + (gm8 >> 8)) * G4;
        }
#pragma unroll
        for (int ni = 0; ni < 4; ni++) {
            float2 v0 = make_float2(c[mi][ni][0] + bias2[ni].x,
                                    c[mi][ni][1] + bias2[ni].y);
            float2 v1 = make_float2(c[mi][ni][2] + bias2[ni].x,
                                    c[mi][ni][3] + bias2[ni].y);
            *(float2*)(r0 + col0 + ni * 8) = v0;
            *(float2*)(r1 + col0 + ni * 8) = v1;
        }
    }
}

// ---------------------------------------------------------------------------
// Persistent LSTM kernel — HMMA recurrence (R14-proven) + xg prefetch:
//   G[16][32b] = W_hh[16][512] (fp16 reg fragments) x H[512][32] (fp16 smem),
//   K split 8 ways across warps, 8-way smem reduce. Counter grid barrier
//   (R14-proven). xg operands prefetched at step top to hide L2/DRAM latency
//   behind the h broadcast + HMMA.
// 128 blocks x 256 threads, 1/SM, all co-resident.
// ---------------------------------------------------------------------------
#define LSTM_BLOCKS 128
#define HSTRW 260                     // hH row stride in 32-bit words
#define LSTM_HH_W (32 * HSTRW)        // 8320 words
#define LSTM_RED_W (512 * 9)          // 4608 words
#define LSTM_SMEM_WORDS (LSTM_HH_W + LSTM_RED_W + 512 + 128 + 16)
#define LSTM_SMEM_BYTES (LSTM_SMEM_WORDS * 4)   // 54336

__device__ __forceinline__ int lstm_grow(int j0, int r) {
    return (r >> 2) * 512 + j0 + (r & 3);   // gate g = r>>2, unit u = r&3
}

__device__ __forceinline__ void grid_barrier() {
    __threadfence();
    __syncthreads();
    if (threadIdx.x == 0) {
        unsigned gen = g_bar_gen;
        unsigned arr = atomicAdd(&g_bar_count, 1u);
        if (arr == gridDim.x - 1) {
            g_bar_count = 0;
            __threadfence();
            g_bar_gen = gen + 1;
        } else {
            while (g_bar_gen == gen) { }
        }
    }
    __syncthreads();
    __threadfence();
}

__global__ __launch_bounds__(256) void lstm_kernel(const float* __restrict__ w_hh,
                                                   const float* __restrict__ b_hh) {
    extern __shared__ uint32_t sw[];
    uint32_t* hH  = sw;                          // [32 b][260 w] fp16x2
    float* sRed   = (float*)(sw + LSTM_HH_W);    // [512 o][9 pad] (8 warps)
    float* sGate  = sRed + LSTM_RED_W;           // [16 r][32 b]
    float* sC     = sGate + 512;                 // [4 u][32 b]
    float* sBh    = sC + 128;                    // [16]
    const uint32_t hHb = smem_u32(hH);

    const int tid = threadIdx.x;
    const int w = tid >> 5;
    const int lane = tid & 31;
    const int g = lane >> 2;
    const int j0 = blockIdx.x * 4;
    const int kw = w * 64;                       // warp's K-slice base (elems)

    // Register-resident W_hh fragments (fp16): rows g / g+8, warp k-slice.
    uint32_t wa[4][4];
    {
        const float* r0p = w_hh + (size_t)lstm_grow(j0, g) * 512;
        const float* r1p = w_hh + (size_t)lstm_grow(j0, g + 8) * 512;
#pragma unroll
        for (int kk = 0; kk < 4; kk++) {
            int kb = kw + kk * 16 + 2 * (lane & 3);
            wa[kk][0] = f16x2(r0p[kb],     r0p[kb + 1]);
            wa[kk][1] = f16x2(r1p[kb],     r1p[kb + 1]);
            wa[kk][2] = f16x2(r0p[kb + 8], r0p[kb + 9]);
            wa[kk][3] = f16x2(r1p[kb + 8], r1p[kb + 9]);
        }
    }
    if (tid < 16) sBh[tid] = b_hh[lstm_grow(j0, tid)];
    if (tid < 128) sC[tid] = 0.f;
    for (int i = tid; i < LSTM_HH_W; i += 256) hH[i] = 0u;   // h(-1) = 0
    __syncthreads();

    // Per-thread reduce coordinates (outputs o=2*tid, 2*tid+1; same row rr)
    const int oo = tid * 2;
    const int rr = oo >> 5;
    const int ob = oo & 31;
    const float bh_r = sBh[rr];
    const float* xgBase = g_xg + (size_t)ob * G4 + lstm_grow(j0, rr);

    for (int ts = 0; ts < TT; ts++) {
        // Prefetch this step's xg contribution (independent of h ordering;
        // hidden behind the broadcast copy + HMMA below)
        const float* xp = xgBase + (size_t)ts * 32 * G4;
        float x0 = xp[0];
        float x1 = xp[G4];

        if (ts > 0) {
            // Broadcast h(t-1): 32KB fp16, linear cp.async (2048 x 16B)
            const __half* src = g_hs_h + (size_t)(ts - 1) * 32 * 512;
#pragma unroll
            for (int ii = 0; ii < 8; ii++) {
                int idx = tid + 256 * ii;          // chunk id
                int b = idx >> 6, cc = idx & 63;
                cp16(hHb + (uint32_t)(b * HSTRW + cc * 4) * 4, src + idx * 8);
            }
            CP_COMMIT();
            CP_WAIT0();
            __syncthreads();
        }

        // HMMA: 4 n-tiles x 4 k-steps over this warp's K-slice
        float acc[4][4];
#pragma unroll
        for (int ni = 0; ni < 4; ni++)
#pragma unroll
            for (int q = 0; q < 4; q++) acc[ni][q] = 0.f;

        const uint32_t* hBase = hH + g * HSTRW + (kw >> 1) + (lane & 3);
#pragma unroll
        for (int kk = 0; kk < 4; kk++) {
#pragma unroll
            for (int ni = 0; ni < 4; ni++) {
                const uint32_t* p = hBase + ni * (8 * HSTRW) + kk * 8;
                uint32_t bf[2] = {p[0], p[4]};
                mma_f16(acc[ni], wa[kk], bf);
            }
        }
        // Partial store: C rows g / g+8, cols 2t,2t+1 per n-tile
#pragma unroll
        for (int ni = 0; ni < 4; ni++) {
            int o0 = g * 32 + ni * 8 + 2 * (lane & 3);
            int o1 = (g + 8) * 32 + ni * 8 + 2 * (lane & 3);
            sRed[o0 * 9 + w]       = acc[ni][0];
            sRed[(o0 + 1) * 9 + w] = acc[ni][1];
            sRed[o1 * 9 + w]       = acc[ni][2];
            sRed[(o1 + 1) * 9 + w] = acc[ni][3];
        }
        __syncthreads();

        // Reduce 8 warp partials, add prefetched xg + b_hh
        {
            const float* pr = sRed + oo * 9;
            float s0 = 0.f, s1 = 0.f;
#pragma unroll
            for (int j = 0; j < 8; j++) { s0 += pr[j]; s1 += pr[9 + j]; }
            sGate[oo]     = s0 + x0 + bh_r;
            sGate[oo + 1] = s1 + x1 + bh_r;
        }
        __syncthreads();

        // Activations + state update (gate order i,f,g,o)
        if (tid < 128) {
            int u = tid & 3, b = tid >> 2;
            float gi = sGate[(0 + u) * 32 + b];
            float gf = sGate[(4 + u) * 32 + b];
            float gg = sGate[(8 + u) * 32 + b];
            float go = sGate[(12 + u) * 32 + b];
            float cc = sC[u * 32 + b];
            float si = 1.f / (1.f + expf(-gi));
            float sf = 1.f / (1.f + expf(-gf));
            float so = 1.f / (1.f + expf(-go));
            cc = sf * cc + si * tanhf(gg);
            float h = so * tanhf(cc);
            sC[u * 32 + b] = cc;
            g_hs_h[(size_t)(ts * 32 + b) * 512 + j0 + u] = __float2half(h);
        }
        grid_barrier();
    }
}

// ---------------------------------------------------------------------------
// Launch
// ---------------------------------------------------------------------------
extern "C" void kernel_launch(void* const* d_in, const int* in_sizes, int n_in,
                              void* d_out, int out_size) {
    const void*  x       = d_in[0];
    const float* embed_w = (const float*)d_in[1];
    const float* w_ih    = (const float*)d_in[2];
    const float* w_hh    = (const float*)d_in[3];
    const float* b_ih    = (const float*)d_in[4];
    const float* b_hh    = (const float*)d_in[5];
    const float* fc_w    = (const float*)d_in[6];
    const float* fc_b    = (const float*)d_in[7];
    const float* ln_w    = (const float*)d_in[8];
    const float* ln_b    = (const float*)d_in[9];

    float* out    = (float*)d_out;
    float* states = out + (size_t)BT * VV;

    __half *emb_h, *wih_h, *fcw_h, *lnw_h;
    cudaGetSymbolAddress((void**)&emb_h, g_emb_h);
    cudaGetSymbolAddress((void**)&wih_h, g_wih_h);
    cudaGetSymbolAddress((void**)&fcw_h, g_fcw_h);
    cudaGetSymbolAddress((void**)&lnw_h, g_lnw_h);

    // 1) decode token indices
    decode_idx_kernel<<<BT / 256, 256>>>(x);

    // 2) pre-convert all GEMM operands to fp16 (RN)
    cvt_f16_kernel<<<(VV * EE / 8) / 256, 256>>>(emb_h, embed_w, VV * EE / 8);
    cvt_f16_kernel<<<(G4 * EE / 8) / 256, 256>>>(wih_h, w_ih, G4 * EE / 8);
    cvt_f16_kernel<<<(VV * HH / 8) / 256, 256>>>(fcw_h, fc_w, VV * HH / 8);
    cvt_f16_kernel<<<(HH * HH / 8) / 256, 256>>>(lnw_h, ln_w, HH * HH / 8);

    // 3) xg = embed[x] @ w_ih^T + b_ih   (tensor fp16, K=256)
    cudaFuncSetAttribute(gemm_f16<8, 2>,
                         cudaFuncAttributeMaxDynamicSharedMemorySize, BMM_SMEM_BYTES);
    gemm_f16<8, 2><<<dim3(G4 / 128, BT / 128), 256, BMM_SMEM_BYTES>>>(
        wih_h, b_ih, nullptr);

    // 4) sequential LSTM (fp32 c / gates; fp16 h; HMMA recurrence)
    cudaFuncSetAttribute(lstm_kernel, cudaFuncAttributeMaxDynamicSharedMemorySize,
                         LSTM_SMEM_BYTES);
    lstm_kernel<<<LSTM_BLOCKS, 256, LSTM_SMEM_BYTES>>>(w_hh, b_hh);

    // 5) out = hs @ fc_w^T + fc_b   (tensor fp16, K=512)
    cudaFuncSetAttribute(gemm_f16<16, 0>,
                         cudaFuncAttributeMaxDynamicSharedMemorySize, BMM_SMEM_BYTES);
    gemm_f16<16, 0><<<dim3(VV / 128, BT / 128), 256, BMM_SMEM_BYTES>>>(
        fcw_h, fc_b, out);

    // 6) states = hs @ ln_w^T + ln_b   (tensor fp16, K=512)
    cudaFuncSetAttribute(gemm_f16<16, 1>,
                         cudaFuncAttributeMaxDynamicSharedMemorySize, BMM_SMEM_BYTES);
    gemm_f16<16, 1><<<dim3(HH / 128, BT / 128), 256, BMM_SMEM_BYTES>>>(
        lnw_h, ln_b, states);
}

// round 17
// speedup vs baseline: 1.4369x; 1.1295x over previous
#include <cuda_runtime.h>
#include <cuda_fp16.h>
#include <math.h>
#include <stdint.h>

// Problem constants
#define BB 32
#define TT 256
#define EE 256
#define HH 512
#define G4 2048          // 4*H
#define VV 32000
#define BT 8192          // B*T

// ---------------------------------------------------------------------------
// Scratch (no allocations allowed -> __device__ globals)
// ---------------------------------------------------------------------------
__device__ int g_idx[BT];
__device__ float g_xg[(size_t)BT * G4];      // [t][b][4H] gate preactivations
__device__ __half g_hs_h[(size_t)BT * HH];   // fp16 [t][b][k] hidden states
__device__ __half g_emb_h[(size_t)VV * EE];  // fp16 embed_w
__device__ __half g_wih_h[(size_t)G4 * EE];  // fp16 w_ih
__device__ __half g_fcw_h[(size_t)VV * HH];  // fp16 fc_w
__device__ __half g_lnw_h[(size_t)HH * HH];  // fp16 ln_w
__device__ unsigned g_bar_count = 0;
__device__ unsigned g_bar_gen2 = 0;

// ---------------------------------------------------------------------------
// Small helpers
// ---------------------------------------------------------------------------
__device__ __forceinline__ uint32_t f16x2(float lo, float hi) {
    uint32_t r;
    asm("cvt.rn.f16x2.f32 %0, %1, %2;" : "=r"(r) : "f"(hi), "f"(lo));
    return r;
}
__device__ __forceinline__ uint32_t smem_u32(const void* p) {
    uint32_t a;
    asm("{ .reg .u64 t; cvta.to.shared.u64 t, %1; cvt.u32.u64 %0, t; }"
        : "=r"(a) : "l"(p));
    return a;
}
__device__ __forceinline__ void cp16(uint32_t dst, const void* src) {
    asm volatile("cp.async.cg.shared.global [%0], [%1], 16;"
                 :: "r"(dst), "l"(src) : "memory");
}
#define CP_COMMIT() asm volatile("cp.async.commit_group;" ::: "memory")
#define CP_WAIT1()  asm volatile("cp.async.wait_group 1;" ::: "memory")
#define CP_WAIT0()  asm volatile("cp.async.wait_group 0;" ::: "memory")

__device__ __forceinline__ void mma_f16(float* c, const uint32_t* a,
                                        const uint32_t* b) {
    asm volatile(
        "mma.sync.aligned.m16n8k16.row.col.f32.f16.f16.f32 "
        "{%0,%1,%2,%3}, {%4,%5,%6,%7}, {%8,%9}, {%0,%1,%2,%3};"
        : "+f"(c[0]), "+f"(c[1]), "+f"(c[2]), "+f"(c[3])
        : "r"(a[0]), "r"(a[1]), "r"(a[2]), "r"(a[3]), "r"(b[0]), "r"(b[1]));
}

// ---------------------------------------------------------------------------
// Token index decode + barrier state reset (runs before the LSTM each launch)
// ---------------------------------------------------------------------------
__global__ void decode_idx_kernel(const void* __restrict__ xin) {
    int i = blockIdx.x * blockDim.x + threadIdx.x;
    if (i == 0) { g_bar_count = 0; g_bar_gen2 = 0; }
    if (i >= BT) return;
    const long long* x64 = (const long long*)xin;
    bool is64 = true;
#pragma unroll
    for (int j = 0; j < 8; j++) {
        long long v = x64[j];
        if (v < 0 || v >= VV) is64 = false;
    }
    g_idx[i] = is64 ? (int)x64[i] : ((const int*)xin)[i];
}

// ---------------------------------------------------------------------------
// Fused fp32 -> fp16 (RN) conversion of all four weight arrays, 8 elem/thread.
// ---------------------------------------------------------------------------
#define N8_EMB (VV * EE / 8)
#define N8_WIH (G4 * EE / 8)
#define N8_FCW (VV * HH / 8)
#define N8_LNW (HH * HH / 8)
#define N8_TOT (N8_EMB + N8_WIH + N8_FCW + N8_LNW)

__global__ void cvt_all_kernel(const float* __restrict__ embed_w,
                               const float* __restrict__ w_ih,
                               const float* __restrict__ fc_w,
                               const float* __restrict__ ln_w) {
    int i = blockIdx.x * blockDim.x + threadIdx.x;
    if (i >= N8_TOT) return;
    const float* src;
    __half* dst;
    int off = i;
    if (off < N8_EMB) { src = embed_w; dst = g_emb_h; }
    else if ((off -= N8_EMB) < N8_WIH) { src = w_ih; dst = g_wih_h; }
    else if ((off -= N8_WIH) < N8_FCW) { src = fc_w; dst = g_fcw_h; }
    else { off -= N8_FCW; src = ln_w; dst = g_lnw_h; }
    float4 v0 = ((const float4*)src)[2 * off];
    float4 v1 = ((const float4*)src)[2 * off + 1];
    uint4 o = make_uint4(f16x2(v0.x, v0.y), f16x2(v0.z, v0.w),
                         f16x2(v1.x, v1.y), f16x2(v1.z, v1.w));
    ((uint4*)dst)[off] = o;
}

// ---------------------------------------------------------------------------
// fp16 mma GEMM (m16n8k16) — unified for xg / fc / ln (proven R12 kernel):
// CTA 128x128, BK=32, 256 threads, 8 warps (2M x 4N), warp tile 64x32.
// Row-major smem tiles, stride 20 words; cp.async.cg staging, 2 stages.
//   MODE 0: fc (A=g_hs_h remap, K=512, out stride VV)
//   MODE 1: ln (A=g_hs_h remap, K=512, out stride HH)
//   MODE 2: xg (A=g_emb_h gathered via g_idx, K=256, out -> g_xg remap)
// ---------------------------------------------------------------------------
#define BS 20
#define BTILE_W (128 * BS)
#define BBUF_W (2 * BTILE_W)
#define BMM_SMEM_BYTES (2 * BBUF_W * 4)   // 40960

template <int KITERS, int MODE>
__global__ __launch_bounds__(256, 2) void gemm_f16(
    const __half* __restrict__ Wh,   // [N][K] fp16
    const float* __restrict__ bias,  // [N]
    float* __restrict__ outp)
{
    constexpr int K = KITERS * 32;
    extern __shared__ uint32_t smem[];
    const uint32_t sbase = smem_u32(smem);
    const int tid = threadIdx.x;
    const int w = tid >> 5;
    const int lane = tid & 31;
    const int g = lane >> 2;
    const int t = lane & 3;
    const int wm = w >> 2;
    const int wn = w & 3;
    const int by = blockIdx.y;
    const int m0 = by * 128;
    const int n0 = blockIdx.x * 128;

    const int srow = tid >> 2;
    const int schk = (tid & 3) * 8;
    const __half* aP[2];
    const __half* bP[2];
#pragma unroll
    for (int q = 0; q < 2; q++) {
        const int r = srow + q * 64;
        if (MODE == 2) {
            aP[q] = g_emb_h + (size_t)g_idx[m0 + r] * EE + schk;
        } else {
            aP[q] = g_hs_h +
                    ((size_t)((by & 1) * 128 + r) * 32 + (size_t)(by >> 1)) * HH +
                    schk;
        }
        bP[q] = Wh + (size_t)(n0 + r) * K + schk;
    }
    const uint32_t stg = sbase + (uint32_t)srow * 80 + (uint32_t)(tid & 3) * 16;

    float c[4][4][4];
#pragma unroll
    for (int mi = 0; mi < 4; mi++)
#pragma unroll
        for (int ni = 0; ni < 4; ni++)
#pragma unroll
            for (int q = 0; q < 4; q++) c[mi][ni][q] = 0.f;

    auto ISSUE = [&](int s) {
        const uint32_t aD = stg + (s & 1) * (BBUF_W * 4);
        const uint32_t bD = aD + BTILE_W * 4;
        const int k0 = s * 32;
#pragma unroll
        for (int q = 0; q < 2; q++) {
            cp16(aD + q * (64 * 80), aP[q] + k0);
            cp16(bD + q * (64 * 80), bP[q] + k0);
        }
        CP_COMMIT();
    };

    ISSUE(0);
    for (int s = 0; s < KITERS; s++) {
        if (s + 1 < KITERS) { ISSUE(s + 1); CP_WAIT1(); }
        else                { CP_WAIT0(); }
        __syncthreads();

        const uint32_t* aC = smem + (s & 1) * BBUF_W + (wm * 64 + g) * BS + t;
        const uint32_t* bC = smem + (s & 1) * BBUF_W + BTILE_W +
                             (wn * 32 + g) * BS + t;
#pragma unroll
        for (int kk = 0; kk < 2; kk++) {
            uint32_t af[4][4];
#pragma unroll
            for (int mi = 0; mi < 4; mi++) {
                const uint32_t* p = aC + mi * (16 * BS) + kk * 8;
                af[mi][0] = p[0];
                af[mi][1] = p[8 * BS];
                af[mi][2] = p[4];
                af[mi][3] = p[8 * BS + 4];
            }
            uint32_t bf[4][2];
#pragma unroll
            for (int ni = 0; ni < 4; ni++) {
                const uint32_t* p = bC + ni * (8 * BS) + kk * 8;
                bf[ni][0] = p[0];
                bf[ni][1] = p[4];
            }
#pragma unroll
            for (int mi = 0; mi < 4; mi++)
#pragma unroll
                for (int ni = 0; ni < 4; ni++)
                    mma_f16(c[mi][ni], af[mi], bf[ni]);
        }
        __syncthreads();
    }

    const int col0 = n0 + wn * 32 + 2 * t;
    float2 bias2[4];
#pragma unroll
    for (int ni = 0; ni < 4; ni++)
        bias2[ni] = *(const float2*)(bias + col0 + ni * 8);
#pragma unroll
    for (int mi = 0; mi < 4; mi++) {
        int gm = m0 + wm * 64 + mi * 16 + g;
        float *r0, *r1;
        if (MODE == 0) {
            r0 = outp + (size_t)gm * VV;
            r1 = outp + (size_t)(gm + 8) * VV;
        } else if (MODE == 1) {
            r0 = outp + (size_t)gm * HH;
            r1 = outp + (size_t)(gm + 8) * HH;
        } else {
            int gm8 = gm + 8;
            r0 = g_xg + (size_t)((gm & 255) * 32 + (gm >> 8)) * G4;
            r1 = g_xg + (size_t)((gm8 & 255) * 32 + (gm8 >> 8)) * G4;
        }
#pragma unroll
        for (int ni = 0; ni < 4; ni++) {
            float2 v0 = make_float2(c[mi][ni][0] + bias2[ni].x,
                                    c[mi][ni][1] + bias2[ni].y);
            float2 v1 = make_float2(c[mi][ni][2] + bias2[ni].x,
                                    c[mi][ni][3] + bias2[ni].y);
            *(float2*)(r0 + col0 + ni * 8) = v0;
            *(float2*)(r1 + col0 + ni * 8) = v1;
        }
    }
}

// ---------------------------------------------------------------------------
// Persistent LSTM kernel — HMMA recurrence (R14/R16-proven math) with:
//   * conflict-free sRed layout: idx(w,r,c) = w*620 + r*33 + c*4
//     (write bank = g+8h+8t, read bank = u+4b: both lane-bijective)
//   * fused reduce+activation phase (sGate eliminated, one less syncthreads;
//     reduction order over warps 0..7 preserved -> identical arithmetic)
//   * fence-free grid barrier: atom.add.acq_rel arrival, st.release gen,
//     ld.acquire poll (expected gen = ts). All cross-SM h reads use
//     cp.async.cg (L1-bypassed); xg is read-only -> no L1 flush needed.
// 128 blocks x 256 threads, 1/SM, all co-resident.
// ---------------------------------------------------------------------------
#define LSTM_BLOCKS 128
#define HSTRW 260                     // hH row stride in 32-bit words
#define LSTM_HH_W (32 * HSTRW)        // 8320 words
#define RSEG 620                      // per-warp sRed segment (words)
#define LSTM_RED_W (8 * RSEG)         // 4960 words
#define LSTM_SMEM_WORDS (LSTM_HH_W + LSTM_RED_W + 128 + 16)
#define LSTM_SMEM_BYTES (LSTM_SMEM_WORDS * 4)   // 53696

__device__ __forceinline__ int lstm_grow(int j0, int r) {
    return (r >> 2) * 512 + j0 + (r & 3);   // gate g = r>>2, unit u = r&3
}

__global__ __launch_bounds__(256) void lstm_kernel(const float* __restrict__ w_hh,
                                                   const float* __restrict__ b_hh) {
    extern __shared__ uint32_t sw[];
    uint32_t* hH  = sw;                          // [32 b][260 w] fp16x2
    float* sRed   = (float*)(sw + LSTM_HH_W);    // 8 x 620 words
    float* sC     = sRed + LSTM_RED_W;           // [4 u][32 b]
    float* sBh    = sC + 128;                    // [16]
    const uint32_t hHb = smem_u32(hH);

    const int tid = threadIdx.x;
    const int w = tid >> 5;
    const int lane = tid & 31;
    const int g = lane >> 2;
    const int j0 = blockIdx.x * 4;
    const int kw = w * 64;                       // warp's K-slice base (elems)

    // Register-resident W_hh fragments (fp16): rows g / g+8, warp k-slice.
    uint32_t wa[4][4];
    {
        const float* r0p = w_hh + (size_t)lstm_grow(j0, g) * 512;
        const float* r1p = w_hh + (size_t)lstm_grow(j0, g + 8) * 512;
#pragma unroll
        for (int kk = 0; kk < 4; kk++) {
            int kb = kw + kk * 16 + 2 * (lane & 3);
            wa[kk][0] = f16x2(r0p[kb],     r0p[kb + 1]);
            wa[kk][1] = f16x2(r1p[kb],     r1p[kb + 1]);
            wa[kk][2] = f16x2(r0p[kb + 8], r0p[kb + 9]);
            wa[kk][3] = f16x2(r1p[kb + 8], r1p[kb + 9]);
        }
    }
    if (tid < 16) sBh[tid] = b_hh[lstm_grow(j0, tid)];
    if (tid < 128) sC[tid] = 0.f;
    for (int i = tid; i < LSTM_HH_W; i += 256) hH[i] = 0u;   // h(-1) = 0
    __syncthreads();

    // Act-thread coordinates (tid < 128): unit u, batch b
    const int au = tid & 3;
    const int ab = tid >> 2;
    float bhv[4];
    const float* xgAct = nullptr;
    if (tid < 128) {
#pragma unroll
        for (int q = 0; q < 4; q++) bhv[q] = sBh[au + 4 * q];
        xgAct = g_xg + (size_t)ab * G4 + j0 + au;   // + ts*32*G4 + q*512
    }

    for (int ts = 0; ts < TT; ts++) {
        // Prefetch xg (independent of h ordering; hidden behind copy + HMMA)
        float xv[4];
        if (tid < 128) {
            const float* xp = xgAct + (size_t)ts * 32 * G4;
#pragma unroll
            for (int q = 0; q < 4; q++) xv[q] = xp[q * 512];
        }

        if (ts > 0) {
            // Broadcast h(t-1): 32KB fp16, linear cp.async (2048 x 16B)
            const __half* src = g_hs_h + (size_t)(ts - 1) * 32 * 512;
#pragma unroll
            for (int ii = 0; ii < 8; ii++) {
                int idx = tid + 256 * ii;
                int b = idx >> 6, cc = idx & 63;
                cp16(hHb + (uint32_t)(b * HSTRW + cc * 4) * 4, src + idx * 8);
            }
            CP_COMMIT();
            CP_WAIT0();
            __syncthreads();
        }

        // HMMA: 4 n-tiles x 4 k-steps over this warp's K-slice
        float acc[4][4];
#pragma unroll
        for (int ni = 0; ni < 4; ni++)
#pragma unroll
            for (int q = 0; q < 4; q++) acc[ni][q] = 0.f;

        const uint32_t* hBase = hH + g * HSTRW + (kw >> 1) + (lane & 3);
#pragma unroll
        for (int kk = 0; kk < 4; kk++) {
#pragma unroll
            for (int ni = 0; ni < 4; ni++) {
                const uint32_t* p = hBase + ni * (8 * HSTRW) + kk * 8;
                uint32_t bf[2] = {p[0], p[4]};
                mma_f16(acc[ni], wa[kk], bf);
            }
        }
        // Partial store (conflict-free): idx = w*RSEG + r*33 + c*4
        {
            float* seg = sRed + w * RSEG;
#pragma unroll
            for (int ni = 0; ni < 4; ni++) {
                int c0 = ni * 8 + 2 * (lane & 3);
                seg[g * 33 + c0 * 4]             = acc[ni][0];
                seg[g * 33 + (c0 + 1) * 4]       = acc[ni][1];
                seg[(g + 8) * 33 + c0 * 4]       = acc[ni][2];
                seg[(g + 8) * 33 + (c0 + 1) * 4] = acc[ni][3];
            }
        }
        __syncthreads();

        // Fused reduce (warps 0..7, order preserved) + activations + update
        if (tid < 128) {
            float gate[4];
#pragma unroll
            for (int q = 0; q < 4; q++) {
                int base = (au + 4 * q) * 33 + ab * 4;
                float s = 0.f;
#pragma unroll
                for (int j = 0; j < 8; j++) s += sRed[j * RSEG + base];
                gate[q] = s + xv[q] + bhv[q];
            }
            float cc = sC[au * 32 + ab];
            float si = 1.f / (1.f + expf(-gate[0]));
            float sf = 1.f / (1.f + expf(-gate[1]));
            float so = 1.f / (1.f + expf(-gate[3]));
            cc = sf * cc + si * tanhf(gate[2]);
            float h = so * tanhf(cc);
            sC[au * 32 + ab] = cc;
            g_hs_h[(size_t)(ts * 32 + ab) * 512 + j0 + au] = __float2half(h);
        }
        __syncthreads();

        // Fence-free grid barrier (expected gen = ts)
        if (tid == 0) {
            unsigned arr;
            asm volatile("atom.add.acq_rel.gpu.global.u32 %0, [%1], 1;"
                         : "=r"(arr) : "l"(&g_bar_count) : "memory");
            if (arr == (unsigned)(LSTM_BLOCKS - 1)) {
                asm volatile("st.relaxed.gpu.global.b32 [%0], %1;"
                             :: "l"(&g_bar_count), "r"(0u) : "memory");
                asm volatile("st.release.gpu.global.b32 [%0], %1;"
                             :: "l"(&g_bar_gen2), "r"((unsigned)(ts + 1))
                             : "memory");
            } else {
                unsigned cur;
                do {
                    asm volatile("ld.acquire.gpu.global.b32 %0, [%1];"
                                 : "=r"(cur) : "l"(&g_bar_gen2) : "memory");
                } while (cur <= (unsigned)ts);
            }
        }
        __syncthreads();
    }
}

// ---------------------------------------------------------------------------
// Launch
// ---------------------------------------------------------------------------
extern "C" void kernel_launch(void* const* d_in, const int* in_sizes, int n_in,
                              void* d_out, int out_size) {
    const void*  x       = d_in[0];
    const float* embed_w = (const float*)d_in[1];
    const float* w_ih    = (const float*)d_in[2];
    const float* w_hh    = (const float*)d_in[3];
    const float* b_ih    = (const float*)d_in[4];
    const float* b_hh    = (const float*)d_in[5];
    const float* fc_w    = (const float*)d_in[6];
    const float* fc_b    = (const float*)d_in[7];
    const float* ln_w    = (const float*)d_in[8];
    const float* ln_b    = (const float*)d_in[9];

    float* out    = (float*)d_out;
    float* states = out + (size_t)BT * VV;

    __half *wih_h, *fcw_h, *lnw_h;
    cudaGetSymbolAddress((void**)&wih_h, g_wih_h);
    cudaGetSymbolAddress((void**)&fcw_h, g_fcw_h);
    cudaGetSymbolAddress((void**)&lnw_h, g_lnw_h);

    // 1) decode token indices + reset barrier state
    decode_idx_kernel<<<BT / 256, 256>>>(x);

    // 2) pre-convert all GEMM operands to fp16 (RN) — single fused launch
    cvt_all_kernel<<<(N8_TOT + 255) / 256, 256>>>(embed_w, w_ih, fc_w, ln_w);

    // 3) xg = embed[x] @ w_ih^T + b_ih   (tensor fp16, K=256)
    cudaFuncSetAttribute(gemm_f16<8, 2>,
                         cudaFuncAttributeMaxDynamicSharedMemorySize, BMM_SMEM_BYTES);
    gemm_f16<8, 2><<<dim3(G4 / 128, BT / 128), 256, BMM_SMEM_BYTES>>>(
        wih_h, b_ih, nullptr);

    // 4) sequential LSTM (fp32 c / gates; fp16 h; HMMA recurrence)
    cudaFuncSetAttribute(lstm_kernel, cudaFuncAttributeMaxDynamicSharedMemorySize,
                         LSTM_SMEM_BYTES);
    lstm_kernel<<<LSTM_BLOCKS, 256, LSTM_SMEM_BYTES>>>(w_hh, b_hh);

    // 5) out = hs @ fc_w^T + fc_b   (tensor fp16, K=512)
    cudaFuncSetAttribute(gemm_f16<16, 0>,
                         cudaFuncAttributeMaxDynamicSharedMemorySize, BMM_SMEM_BYTES);
    gemm_f16<16, 0><<<dim3(VV / 128, BT / 128), 256, BMM_SMEM_BYTES>>>(
        fcw_h, fc_b, out);

    // 6) states = hs @ ln_w^T + ln_b   (tensor fp16, K=512)
    cudaFuncSetAttribute(gemm_f16<16, 1>,
                         cudaFuncAttributeMaxDynamicSharedMemorySize, BMM_SMEM_BYTES);
    gemm_f16<16, 1><<<dim3(HH / 128, BT / 128), 256, BMM_SMEM_BYTES>>>(
        lnw_h, ln_b, states);
}